// round 1
// baseline (speedup 1.0000x reference)
#include <cuda_runtime.h>
#include <math.h>

// Problem constants
#define BB   64      // batch
#define TT   128     // window
#define HH   50      // lstm hidden
#define VV   8192    // vocab
#define G4H  200     // 4*H
#define PP   64      // T/2
#define MM   4096    // B * T/2

// ---------------- scratch (static device globals; no allocs) ----------------
__device__ float g_Ewx[VV * G4H];              // E@Wx + b   (6.55 MB)
__device__ float g_pooled[MM * 64];            // maxpooled LSTM out, K padded to 64 (1 MB)
__device__ float g_W1pad[64 * VV];             // W1 zero-padded to K=64 (2 MB)
__device__ float g_x1[(size_t)MM * VV];        // 134 MB
__device__ float g_x2[(size_t)MM * VV];        // 134 MB

__device__ __forceinline__ float sigf(float x) { return 1.0f / (1.0f + expf(-x)); }

// packed dual-FMA: d(2xf32) += a(2xf32) * b(2xf32)
__device__ __forceinline__ void ffma2(unsigned long long& d, unsigned long long a, unsigned long long b) {
    asm("fma.rn.f32x2 %0, %1, %2, %0;" : "+l"(d) : "l"(a), "l"(b));
}

// ---------------- kernel 1: Ewx[v][k] = sum_h E[v][h]*Wx[h][k] + b[k] ----------------
__global__ void ewx_kernel(const float* __restrict__ E, const float* __restrict__ Wx,
                           const float* __restrict__ bias) {
    __shared__ float e[HH];
    int v = blockIdx.x;
    if (threadIdx.x < HH) e[threadIdx.x] = E[v * HH + threadIdx.x];
    __syncthreads();
    int k = threadIdx.x;
    if (k < G4H) {
        float acc = bias[k];
#pragma unroll
        for (int h = 0; h < HH; ++h) acc = fmaf(e[h], Wx[h * G4H + k], acc);
        g_Ewx[(size_t)v * G4H + k] = acc;
    }
}

// ---------------- kernel 2: pad W1 [50,V] -> [64,V] with zeros ----------------
__global__ void w1pad_kernel(const float* __restrict__ W1) {
    int i = blockIdx.x * 256 + threadIdx.x;
    if (i < 64 * VV) {
        int k = i >> 13;           // V = 2^13
        int n = i & (VV - 1);
        g_W1pad[i] = (k < HH) ? W1[k * VV + n] : 0.0f;
    }
}

// ---------------- kernel 3: LSTM scan + fused MaxPool(2) ----------------
// One block per batch element. U kept in SMEM. Gate order i,f,c,o.
__global__ void lstm_kernel(const int* __restrict__ inp, const float* __restrict__ U,
                            const float* __restrict__ rec_mask) {
    __shared__ float sU[4 * HH * HH];   // 40 KB
    __shared__ float rm[G4H], hm[G4H], z[G4H];
    __shared__ float h[HH], c[HH], hprev[HH];
    int b = blockIdx.x, tid = threadIdx.x;

    for (int i = tid; i < 4 * HH * HH; i += 256) sU[i] = U[i];
    if (tid < G4H) {
        int g = tid / HH, j = tid - g * HH;
        rm[tid] = rec_mask[((size_t)g * BB + b) * HH + j];
    }
    if (tid < HH) { h[tid] = 0.0f; c[tid] = 0.0f; hprev[tid] = 0.0f; }
    __syncthreads();

    for (int t = 0; t < TT; ++t) {
        if (tid < G4H) hm[tid] = h[tid % HH] * rm[tid];
        __syncthreads();
        if (tid < G4H) {
            int g = tid / HH, j = tid - g * HH;
            float acc = g_Ewx[(size_t)inp[b * TT + t] * G4H + tid];
            const float* Ug = sU + g * HH * HH + j;
            const float* hg = hm + g * HH;
#pragma unroll
            for (int k = 0; k < HH; ++k) acc = fmaf(hg[k], Ug[k * HH], acc);
            z[tid] = acc;
        }
        __syncthreads();
        if (tid < HH) {
            float iv = sigf(z[tid]);
            float fv = sigf(z[HH + tid]);
            float gv = tanhf(z[2 * HH + tid]);
            float ov = sigf(z[3 * HH + tid]);
            float cn = fv * c[tid] + iv * gv;
            float hn = ov * tanhf(cn);
            c[tid] = cn;
            h[tid] = hn;
            if (t & 1) g_pooled[((size_t)b * PP + (t >> 1)) * 64 + tid] = fmaxf(hprev[tid], hn);
            else       hprev[tid] = hn;
        } else if (tid < 64 && (t & 1)) {
            g_pooled[((size_t)b * PP + (t >> 1)) * 64 + tid] = 0.0f;   // zero K-padding
        }
        __syncthreads();
    }
}

// ---------------- kernel 4: fp32x2 SGEMM, 128x128x8 tiles, fused epilogue ----------------
// C[M=4096, N=8192] = epi(A[M,K] @ B[K,N] + bias)   (K % 8 == 0)
// EPI==0: relu(x+bias)*mask   EPI==1: sigmoid(x+bias)
template <int EPI>
__global__ __launch_bounds__(256) void gemm_kernel(const float* __restrict__ A,
                                                   const float* __restrict__ B,
                                                   float* __restrict__ C, int K,
                                                   const float* __restrict__ bias,
                                                   const float* __restrict__ mask) {
    constexpr int BM = 128, BN = 128, BK = 8;
    __shared__ __align__(16) float2 As2[BK * BM];  // A values duplicated into f32x2 pairs
    __shared__ __align__(16) float  Bs[BK * BN];

    int tid = threadIdx.x;
    int bm = blockIdx.y * BM;
    int bn = blockIdx.x * BN;
    // thread microtile: rows {m0..m0+3, m0+64..m0+67}, cols {n0..n0+3, n0+64..n0+67}
    int m0 = (tid >> 4) * 4;
    int n0 = (tid & 15) * 4;
    int a_r = tid >> 1, a_c = (tid & 1) * 4;
    int b_r = tid >> 5, b_c = (tid & 31) * 4;

    unsigned long long acc[8][4];
#pragma unroll
    for (int i = 0; i < 8; ++i)
#pragma unroll
        for (int j = 0; j < 4; ++j) acc[i][j] = 0ull;

    const float* Aptr = A + (size_t)(bm + a_r) * K + a_c;
    const float* Bptr = B + (size_t)b_r * VV + bn + b_c;

    float4 va = *(const float4*)Aptr;
    float4 vb = *(const float4*)Bptr;

    for (int k0 = 0; k0 < K; k0 += BK) {
        As2[(a_c + 0) * BM + a_r] = make_float2(va.x, va.x);
        As2[(a_c + 1) * BM + a_r] = make_float2(va.y, va.y);
        As2[(a_c + 2) * BM + a_r] = make_float2(va.z, va.z);
        As2[(a_c + 3) * BM + a_r] = make_float2(va.w, va.w);
        *(float4*)&Bs[b_r * BN + b_c] = vb;
        __syncthreads();
        if (k0 + BK < K) {   // register prefetch of next tile
            va = *(const float4*)(Aptr + k0 + BK);
            vb = *(const float4*)(Bptr + (size_t)(k0 + BK) * VV);
        }
#pragma unroll
        for (int kk = 0; kk < BK; ++kk) {
            const unsigned long long* au = (const unsigned long long*)(As2 + kk * BM);
            ulonglong2 A0 = *(const ulonglong2*)(au + m0);
            ulonglong2 A1 = *(const ulonglong2*)(au + m0 + 2);
            ulonglong2 A2 = *(const ulonglong2*)(au + m0 + 64);
            ulonglong2 A3 = *(const ulonglong2*)(au + m0 + 66);
            ulonglong2 B0 = *(const ulonglong2*)(Bs + kk * BN + n0);
            ulonglong2 B1 = *(const ulonglong2*)(Bs + kk * BN + n0 + 64);
            unsigned long long rmv[8] = {A0.x, A0.y, A1.x, A1.y, A2.x, A2.y, A3.x, A3.y};
            unsigned long long rnv[4] = {B0.x, B0.y, B1.x, B1.y};
#pragma unroll
            for (int i = 0; i < 8; ++i)
#pragma unroll
                for (int j = 0; j < 4; ++j) ffma2(acc[i][j], rmv[i], rnv[j]);
        }
        __syncthreads();
    }

    float4 bv0 = *(const float4*)&bias[bn + n0];
    float4 bv1 = *(const float4*)&bias[bn + n0 + 64];
#pragma unroll
    for (int mi = 0; mi < 8; ++mi) {
        int row = bm + m0 + (mi & 3) + ((mi >> 2) << 6);
        size_t base = (size_t)row * VV + bn;
        float2 c0 = *(float2*)&acc[mi][0];
        float2 c1 = *(float2*)&acc[mi][1];
        float2 c2 = *(float2*)&acc[mi][2];
        float2 c3 = *(float2*)&acc[mi][3];
        float4 r0 = make_float4(c0.x + bv0.x, c0.y + bv0.y, c1.x + bv0.z, c1.y + bv0.w);
        float4 r1 = make_float4(c2.x + bv1.x, c2.y + bv1.y, c3.x + bv1.z, c3.y + bv1.w);
        if (EPI == 0) {
            float4 mk0 = *(const float4*)&mask[base + n0];
            float4 mk1 = *(const float4*)&mask[base + n0 + 64];
            r0.x = fmaxf(r0.x, 0.0f) * mk0.x;  r0.y = fmaxf(r0.y, 0.0f) * mk0.y;
            r0.z = fmaxf(r0.z, 0.0f) * mk0.z;  r0.w = fmaxf(r0.w, 0.0f) * mk0.w;
            r1.x = fmaxf(r1.x, 0.0f) * mk1.x;  r1.y = fmaxf(r1.y, 0.0f) * mk1.y;
            r1.z = fmaxf(r1.z, 0.0f) * mk1.z;  r1.w = fmaxf(r1.w, 0.0f) * mk1.w;
        } else {
            r0.x = sigf(r0.x); r0.y = sigf(r0.y); r0.z = sigf(r0.z); r0.w = sigf(r0.w);
            r1.x = sigf(r1.x); r1.y = sigf(r1.y); r1.z = sigf(r1.z); r1.w = sigf(r1.w);
        }
        *(float4*)&C[base + n0]      = r0;
        *(float4*)&C[base + n0 + 64] = r1;
    }
}

// ---------------- launch ----------------
extern "C" void kernel_launch(void* const* d_in, const int* in_sizes, int n_in,
                              void* d_out, int out_size) {
    const int*   inp      = (const int*)  d_in[0];
    const float* E        = (const float*)d_in[1];
    const float* Wx       = (const float*)d_in[2];
    const float* U        = (const float*)d_in[3];
    const float* bb       = (const float*)d_in[4];
    const float* W1       = (const float*)d_in[5];
    const float* b1       = (const float*)d_in[6];
    const float* W1b      = (const float*)d_in[7];
    const float* W2       = (const float*)d_in[8];
    const float* b2       = (const float*)d_in[9];
    const float* rec_mask = (const float*)d_in[10];
    const float* dmask1   = (const float*)d_in[11];
    const float* dmask2   = (const float*)d_in[12];
    float* out = (float*)d_out;

    void *p_pooled, *p_w1pad, *p_x1, *p_x2;
    cudaGetSymbolAddress(&p_pooled, g_pooled);
    cudaGetSymbolAddress(&p_w1pad, g_W1pad);
    cudaGetSymbolAddress(&p_x1, g_x1);
    cudaGetSymbolAddress(&p_x2, g_x2);

    ewx_kernel<<<VV, 256>>>(E, Wx, bb);
    w1pad_kernel<<<(64 * VV) / 256, 256>>>(W1);
    lstm_kernel<<<BB, 256>>>(inp, U, rec_mask);

    dim3 grid(VV / 128, MM / 128);
    // GEMM1: x1 = relu(pooled @ W1 + b1) * dmask1     (K = 64, zero-padded)
    gemm_kernel<0><<<grid, 256>>>((const float*)p_pooled, (const float*)p_w1pad,
                                  (float*)p_x1, 64, b1, dmask1);
    // GEMM2: x2 = relu(x1 @ W1b + b1) * dmask2        (K = 8192)
    gemm_kernel<0><<<grid, 256>>>((const float*)p_x1, W1b, (float*)p_x2, VV, b1, dmask2);
    // GEMM3: out = sigmoid(x2 @ W2 + b2)              (K = 8192)
    gemm_kernel<1><<<grid, 256>>>((const float*)p_x2, W2, out, VV, b2, nullptr);
}

// round 3
// speedup vs baseline: 7.0994x; 7.0994x over previous
#include <cuda_runtime.h>
#include <cuda_fp16.h>
#include <math.h>
#include <stdint.h>

#define BB   64
#define TT   128
#define HH   50
#define VV   8192
#define G4H  200
#define PP   64
#define MM   4096

typedef __half h16;

// ---------------- helpers ----------------
__device__ __forceinline__ uint32_t smem_u32(const void* p) {
    uint32_t a;
    asm("{ .reg .u64 t; cvta.to.shared.u64 t, %1; cvt.u32.u64 %0, t; }" : "=r"(a) : "l"(p));
    return a;
}
__device__ __forceinline__ void cp16(uint32_t saddr, const void* gptr) {
    asm volatile("cp.async.cg.shared.global [%0], [%1], 16;" :: "r"(saddr), "l"(gptr));
}
__device__ __forceinline__ void ldsm4(uint32_t& r0, uint32_t& r1, uint32_t& r2, uint32_t& r3, uint32_t addr) {
    asm volatile("ldmatrix.sync.aligned.m8n8.x4.shared.b16 {%0,%1,%2,%3}, [%4];"
                 : "=r"(r0), "=r"(r1), "=r"(r2), "=r"(r3) : "r"(addr));
}
__device__ __forceinline__ void mma16816(float* c, const uint32_t* a, const uint32_t* b) {
    asm volatile("mma.sync.aligned.m16n8k16.row.col.f32.f16.f16.f32 "
                 "{%0,%1,%2,%3}, {%4,%5,%6,%7}, {%8,%9}, {%0,%1,%2,%3};"
                 : "+f"(c[0]), "+f"(c[1]), "+f"(c[2]), "+f"(c[3])
                 : "r"(a[0]), "r"(a[1]), "r"(a[2]), "r"(a[3]), "r"(b[0]), "r"(b[1]));
}
__device__ __forceinline__ float sigf(float x) { return 1.0f / (1.0f + expf(-x)); }

// ---------------- scratch globals ----------------
__device__ __align__(256) float g_Ewx[VV * G4H];
__device__ __align__(256) h16 g_pooled[MM * 64];
__device__ __align__(256) h16 g_W1t[VV * 64];
__device__ __align__(256) h16 g_W1bt[(size_t)VV * VV];
__device__ __align__(256) h16 g_W2t[(size_t)VV * VV];
__device__ __align__(256) h16 g_x1[(size_t)MM * VV];
__device__ __align__(256) h16 g_x2[(size_t)MM * VV];

// ---------------- kernel 1: Ewx = E@Wx + b (fp32) ----------------
__global__ void ewx_kernel(const float* __restrict__ E, const float* __restrict__ Wx,
                           const float* __restrict__ bias) {
    __shared__ float e[HH];
    int v = blockIdx.x;
    if (threadIdx.x < HH) e[threadIdx.x] = E[v * HH + threadIdx.x];
    __syncthreads();
    int k = threadIdx.x;
    if (k < G4H) {
        float acc = bias[k];
#pragma unroll
        for (int h = 0; h < HH; ++h) acc = fmaf(e[h], Wx[h * G4H + k], acc);
        g_Ewx[(size_t)v * G4H + k] = acc;
    }
}

// ---------------- kernel 2: W1 [50,V] -> W1t [V,64] fp16 (zero pad K) ----------------
__global__ void w1t_kernel(const float* __restrict__ W1) {
    int i = blockIdx.x * 256 + threadIdx.x;   // n*64 + k
    int n = i >> 6, k = i & 63;
    float v = (k < HH) ? W1[(size_t)k * VV + n] : 0.0f;
    g_W1t[i] = __float2half_rn(v);
}

// ---------------- kernel 3: transpose-convert W [K=V][N=V] fp32 -> Wt [N][K] fp16 ----------------
__global__ void convT_kernel(const float* __restrict__ W, h16* __restrict__ Wt) {
    __shared__ float t[32][33];
    int tx = threadIdx.x, ty = threadIdx.y;
    int col = blockIdx.x * 32 + tx;
#pragma unroll
    for (int i = 0; i < 32; i += 8) {
        int row = blockIdx.y * 32 + ty + i;
        t[ty + i][tx] = W[(size_t)row * VV + col];
    }
    __syncthreads();
#pragma unroll
    for (int i = 0; i < 32; i += 8) {
        int n = blockIdx.x * 32 + ty + i;
        int k = blockIdx.y * 32 + tx;
        Wt[(size_t)n * VV + k] = __float2half_rn(t[tx][ty + i]);
    }
}

// ---------------- kernel 4: LSTM scan + fused MaxPool(2), fp16 out ----------------
__global__ void lstm_kernel(const int* __restrict__ inp, const float* __restrict__ U,
                            const float* __restrict__ rec_mask) {
    __shared__ float sU[4 * HH * HH];
    __shared__ float rm[G4H], hm[G4H], z[G4H];
    __shared__ float h[HH], c[HH], hprev[HH];
    int b = blockIdx.x, tid = threadIdx.x;

    for (int i = tid; i < 4 * HH * HH; i += 256) sU[i] = U[i];
    if (tid < G4H) {
        int g = tid / HH, j = tid - g * HH;
        rm[tid] = rec_mask[((size_t)g * BB + b) * HH + j];
    }
    if (tid < HH) { h[tid] = 0.0f; c[tid] = 0.0f; hprev[tid] = 0.0f; }
    __syncthreads();

    for (int t = 0; t < TT; ++t) {
        if (tid < G4H) hm[tid] = h[tid % HH] * rm[tid];
        __syncthreads();
        if (tid < G4H) {
            int g = tid / HH, j = tid - g * HH;
            float acc = g_Ewx[(size_t)inp[b * TT + t] * G4H + tid];
            const float* Ug = sU + g * HH * HH + j;
            const float* hg = hm + g * HH;
#pragma unroll
            for (int k = 0; k < HH; ++k) acc = fmaf(hg[k], Ug[k * HH], acc);
            z[tid] = acc;
        }
        __syncthreads();
        if (tid < HH) {
            float iv = sigf(z[tid]);
            float fv = sigf(z[HH + tid]);
            float gv = tanhf(z[2 * HH + tid]);
            float ov = sigf(z[3 * HH + tid]);
            float cn = fv * c[tid] + iv * gv;
            float hn = ov * tanhf(cn);
            c[tid] = cn;
            h[tid] = hn;
            if (t & 1) {
                g_pooled[((size_t)b * PP + (t >> 1)) * 64 + tid] = __float2half_rn(fmaxf(hprev[tid], hn));
            } else hprev[tid] = hn;
        } else if (tid < 64 && (t & 1)) {
            g_pooled[((size_t)b * PP + (t >> 1)) * 64 + tid] = __float2half_rn(0.0f);
        }
        __syncthreads();
    }
}

// ---------------- kernel 5: fp16 HMMA GEMM, 128x128x32, 4-stage cp.async ----------------
// C[M=4096, N=8192] = epi(A[M,K] @ B[N,K]^T + bias)
// EPI 0: relu(+bias)*mask -> fp16.  EPI 1: sigmoid(+bias) -> fp32.
#define GBM 128
#define GBN 128
#define BKH 32
#define RSB 80                      // smem row stride bytes (64B data + 16B pad)
#define A_BYTES (GBM * RSB)         // 10240
#define STAGE (2 * GBM * RSB)       // 20480
#define GSMEM (4 * STAGE)           // 81920

template <int EPI>
__global__ void __launch_bounds__(256) hgemm(
    const h16* __restrict__ A, const h16* __restrict__ B, int K,
    const float* __restrict__ bias, const float* __restrict__ mask,
    h16* __restrict__ outh, float* __restrict__ outf) {
    extern __shared__ char smem[];
    uint32_t sb = smem_u32(smem);
    int tid = threadIdx.x, lid = tid & 31, wid = tid >> 5;
    int wm = wid >> 2, wn = wid & 3;   // warp grid 2x4 (M x N)

    // GROUP_M=16 rasterization
    const int NTN = VV / GBN;          // 64
    int pid = blockIdx.x;
    int npg = 16 * NTN;
    int gid = pid / npg;
    int pm = gid * 16 + (pid % 16);
    int pn = (pid % npg) / 16;
    int bm = pm * GBM, bn = pn * GBN;

    // cp.async thread mapping: chunk idx = tid + it*256; row = idx>>2, ch = idx&3
    int lrow = tid >> 2, lch = tid & 3;
    const h16* gA = A + (size_t)bm * K;
    const h16* gB = B + (size_t)bn * K;

    // ldmatrix per-thread base byte offsets
    uint32_t aoff = (uint32_t)((wm * 64 + (lid & 15)) * RSB + (lid >> 4) * 16);
    uint32_t boff = (uint32_t)((wn * 32 + (lid & 7) + ((lid >> 4) << 3)) * RSB + ((lid >> 3) & 1) * 16);

    float acc[4][4][4];
#pragma unroll
    for (int i = 0; i < 4; ++i)
#pragma unroll
        for (int j = 0; j < 4; ++j)
#pragma unroll
            for (int q = 0; q < 4; ++q) acc[i][j][q] = 0.0f;

    int nk = K / BKH;

    auto load = [&](int s) {
        uint32_t base = sb + (uint32_t)(s & 3) * STAGE;
        int k0 = s * BKH;
#pragma unroll
        for (int it = 0; it < 2; ++it) {
            int row = lrow + it * 64;
            uint32_t so = (uint32_t)(row * RSB + lch * 16);
            cp16(base + so, gA + (size_t)row * K + k0 + lch * 8);
            cp16(base + A_BYTES + so, gB + (size_t)row * K + k0 + lch * 8);
        }
    };

#pragma unroll
    for (int i = 0; i < 3; ++i) {
        if (i < nk) load(i);
        asm volatile("cp.async.commit_group;" ::: "memory");
    }

    for (int s = 0; s < nk; ++s) {
        asm volatile("cp.async.wait_group 2;" ::: "memory");
        __syncthreads();
        uint32_t base = sb + (uint32_t)(s & 3) * STAGE;
        uint32_t Ab = base + aoff;
        uint32_t Bb = base + A_BYTES + boff;
#pragma unroll
        for (int tk = 0; tk < 2; ++tk) {
            uint32_t a[4][4], bf[4][2];
#pragma unroll
            for (int mi = 0; mi < 4; ++mi)
                ldsm4(a[mi][0], a[mi][1], a[mi][2], a[mi][3], Ab + mi * (16 * RSB) + tk * 32);
#pragma unroll
            for (int nj = 0; nj < 2; ++nj) {
                uint32_t t0, t1, t2, t3;
                ldsm4(t0, t1, t2, t3, Bb + nj * (16 * RSB) + tk * 32);
                bf[nj * 2][0] = t0; bf[nj * 2][1] = t1;
                bf[nj * 2 + 1][0] = t2; bf[nj * 2 + 1][1] = t3;
            }
#pragma unroll
            for (int mi = 0; mi < 4; ++mi)
#pragma unroll
                for (int nj = 0; nj < 4; ++nj) mma16816(acc[mi][nj], a[mi], bf[nj]);
        }
        if (s + 3 < nk) load(s + 3);
        asm volatile("cp.async.commit_group;" ::: "memory");
    }

    // epilogue
#pragma unroll
    for (int mi = 0; mi < 4; ++mi) {
        int rbase = bm + wm * 64 + mi * 16 + (lid >> 2);
#pragma unroll
        for (int nj = 0; nj < 4; ++nj) {
            int cn = bn + wn * 32 + nj * 8 + (lid & 3) * 2;
            float2 bv = *(const float2*)&bias[cn];
#pragma unroll
            for (int hh = 0; hh < 2; ++hh) {
                int row = rbase + hh * 8;
                size_t o = (size_t)row * VV + cn;
                float v0 = acc[mi][nj][hh * 2 + 0] + bv.x;
                float v1 = acc[mi][nj][hh * 2 + 1] + bv.y;
                if (EPI == 0) {
                    float2 mk = *(const float2*)&mask[o];
                    v0 = fmaxf(v0, 0.0f) * mk.x;
                    v1 = fmaxf(v1, 0.0f) * mk.y;
                    *(__half2*)(outh + o) = __floats2half2_rn(v0, v1);
                } else {
                    float2 rr;
                    rr.x = sigf(v0); rr.y = sigf(v1);
                    *(float2*)(outf + o) = rr;
                }
            }
        }
    }
}

// ---------------- launch ----------------
extern "C" void kernel_launch(void* const* d_in, const int* in_sizes, int n_in,
                              void* d_out, int out_size) {
    const int*   inp      = (const int*)  d_in[0];
    const float* E        = (const float*)d_in[1];
    const float* Wx       = (const float*)d_in[2];
    const float* U        = (const float*)d_in[3];
    const float* bb       = (const float*)d_in[4];
    const float* W1       = (const float*)d_in[5];
    const float* b1       = (const float*)d_in[6];
    const float* W1b      = (const float*)d_in[7];
    const float* W2       = (const float*)d_in[8];
    const float* b2       = (const float*)d_in[9];
    const float* rec_mask = (const float*)d_in[10];
    const float* dmask1   = (const float*)d_in[11];
    const float* dmask2   = (const float*)d_in[12];
    float* out = (float*)d_out;

    void *p_pooled, *p_w1t, *p_wbt, *p_w2t, *p_x1, *p_x2;
    cudaGetSymbolAddress(&p_pooled, g_pooled);
    cudaGetSymbolAddress(&p_w1t, g_W1t);
    cudaGetSymbolAddress(&p_wbt, g_W1bt);
    cudaGetSymbolAddress(&p_w2t, g_W2t);
    cudaGetSymbolAddress(&p_x1, g_x1);
    cudaGetSymbolAddress(&p_x2, g_x2);

    cudaFuncSetAttribute(hgemm<0>, cudaFuncAttributeMaxDynamicSharedMemorySize, GSMEM);
    cudaFuncSetAttribute(hgemm<1>, cudaFuncAttributeMaxDynamicSharedMemorySize, GSMEM);

    ewx_kernel<<<VV, 256>>>(E, Wx, bb);
    w1t_kernel<<<(VV * 64) / 256, 256>>>(W1);
    convT_kernel<<<dim3(256, 256), dim3(32, 8)>>>(W1b, (h16*)p_wbt);
    convT_kernel<<<dim3(256, 256), dim3(32, 8)>>>(W2, (h16*)p_w2t);
    lstm_kernel<<<BB, 256>>>(inp, U, rec_mask);

    const int grid = (MM / GBM) * (VV / GBN);   // 32 * 64 = 2048
    // GEMM1: x1 = relu(pooled @ W1 + b1) * dmask1   (K = 64)
    hgemm<0><<<grid, 256, GSMEM>>>((const h16*)p_pooled, (const h16*)p_w1t, 64,
                                   b1, dmask1, (h16*)p_x1, nullptr);
    // GEMM2: x2 = relu(x1 @ W1b + b1) * dmask2      (K = 8192)
    hgemm<0><<<grid, 256, GSMEM>>>((const h16*)p_x1, (const h16*)p_wbt, VV,
                                   b1, dmask2, (h16*)p_x2, nullptr);
    // GEMM3: out = sigmoid(x2 @ W2 + b2)            (K = 8192)
    hgemm<1><<<grid, 256, GSMEM>>>((const h16*)p_x2, (const h16*)p_w2t, VV,
                                   b2, nullptr, nullptr, out);
}